// round 7
// baseline (speedup 1.0000x reference)
#include <cuda_runtime.h>
#include <cuda_fp16.h>
#include <math.h>
#include <stdint.h>

// Problem dims (fixed by the reference)
#define BATCH 256
#define NPIX  196
#define CDIM  2048
#define ADIM  512
#define LDIM  512
#define MTOT  (BATCH * NPIX)   // 50176 = 784 * 64

// GEMM tiling (mma.sync m16n8k16)
#define BM 64
#define BN 256
#define BK 16
#define NBLK (ADIM / BN)       // 2
#define NITER (CDIM / BK)      // 128
#define LOSCALE 2048.0f

// Scratch (device globals — no allocation allowed)
__device__ float g_att2[BATCH * ADIM];
__device__ float g_att_part[NBLK * MTOT];
__device__ float g_alpha[MTOT];
__device__ __half g_Wc_hi[ADIM * CDIM];
__device__ __half g_Wc_lo[ADIM * CDIM];   // (Wc - hi) * 2048

// smem: row stride 48B (16 fp16 + 8B pad)
#define ROWB 48
#define BUFSZ 30720
#define SM_A_HI(b) ((b) * BUFSZ + 0)
#define SM_A_LO(b) ((b) * BUFSZ + 3072)
#define SM_B_HI(b) ((b) * BUFSZ + 6144)
#define SM_B_LO(b) ((b) * BUFSZ + 18432)
#define SMEM_BYTES (2 * BUFSZ)

__device__ __forceinline__ uint32_t smem_to_u32(const void* p) {
    uint32_t a;
    asm("{ .reg .u64 t; cvta.to.shared.u64 t, %1; cvt.u32.u64 %0, t; }" : "=r"(a) : "l"(p));
    return a;
}
__device__ __forceinline__ void ldsm4(uint32_t* r, uint32_t addr) {
    asm volatile("ldmatrix.sync.aligned.m8n8.x4.shared.b16 {%0,%1,%2,%3}, [%4];"
                 : "=r"(r[0]), "=r"(r[1]), "=r"(r[2]), "=r"(r[3]) : "r"(addr));
}
__device__ __forceinline__ void mma_f32(float* c, const uint32_t* a, const uint32_t* b) {
    asm volatile("mma.sync.aligned.m16n8k16.row.col.f32.f16.f16.f32 "
                 "{%0,%1,%2,%3}, {%4,%5,%6,%7}, {%8,%9}, {%0,%1,%2,%3};"
                 : "+f"(c[0]), "+f"(c[1]), "+f"(c[2]), "+f"(c[3])
                 : "r"(a[0]), "r"(a[1]), "r"(a[2]), "r"(a[3]), "r"(b[0]), "r"(b[1]));
}
__device__ __forceinline__ void mma_f16(uint32_t* c, const uint32_t* a, const uint32_t* b) {
    asm volatile("mma.sync.aligned.m16n8k16.row.col.f16.f16.f16.f16 "
                 "{%0,%1}, {%2,%3,%4,%5}, {%6,%7}, {%0,%1};"
                 : "+r"(c[0]), "+r"(c[1])
                 : "r"(a[0]), "r"(a[1]), "r"(a[2]), "r"(a[3]), "r"(b[0]), "r"(b[1]));
}
#define CP_ASYNC16(dst, src) \
    asm volatile("cp.async.cg.shared.global [%0], [%1], 16;" :: "r"(dst), "l"(src))
#define CP_COMMIT() asm volatile("cp.async.commit_group;" ::: "memory")
#define CP_WAIT0()  asm volatile("cp.async.wait_group 0;" ::: "memory")

__device__ __forceinline__ uint32_t pack_h(__half a, __half b) {
    return (uint32_t)__half_as_ushort(a) | ((uint32_t)__half_as_ushort(b) << 16);
}

// ---------------------------------------------------------------------------
// K0: convert Wc -> fp16 hi + scaled lo
// ---------------------------------------------------------------------------
__global__ void convert_wc_kernel(const float* __restrict__ Wc) {
    const int i4 = blockIdx.x * 256 + threadIdx.x;
    float4 v = reinterpret_cast<const float4*>(Wc)[i4];
    __half h0 = __float2half(v.x), h1 = __float2half(v.y);
    __half h2 = __float2half(v.z), h3 = __float2half(v.w);
    __half l0 = __float2half((v.x - __half2float(h0)) * LOSCALE);
    __half l1 = __float2half((v.y - __half2float(h1)) * LOSCALE);
    __half l2 = __float2half((v.z - __half2float(h2)) * LOSCALE);
    __half l3 = __float2half((v.w - __half2float(h3)) * LOSCALE);
    reinterpret_cast<uint2*>(g_Wc_hi)[i4] = make_uint2(pack_h(h0, h1), pack_h(h2, h3));
    reinterpret_cast<uint2*>(g_Wc_lo)[i4] = make_uint2(pack_h(l0, l1), pack_h(l2, l3));
}

// ---------------------------------------------------------------------------
// K1: att2[b][a] = lstm[b] . Wl[a] + bl[a]
// ---------------------------------------------------------------------------
__global__ void att2_kernel(const float* __restrict__ lstm,
                            const float* __restrict__ Wl,
                            const float* __restrict__ bl,
                            float* __restrict__ att2) {
    __shared__ float h[8][LDIM];
    const int b0 = blockIdx.x * 8;
    const int a = threadIdx.x;
    #pragma unroll
    for (int i = 0; i < 8; i++) h[i][a] = lstm[(b0 + i) * LDIM + a];
    __syncthreads();
    const float4* w4 = reinterpret_cast<const float4*>(Wl + (size_t)a * LDIM);
    float acc[8] = {0.f, 0.f, 0.f, 0.f, 0.f, 0.f, 0.f, 0.f};
    #pragma unroll 4
    for (int l4 = 0; l4 < LDIM / 4; l4++) {
        float4 wv = w4[l4];
        int l = l4 * 4;
        #pragma unroll
        for (int i = 0; i < 8; i++) {
            acc[i] += h[i][l + 0] * wv.x;
            acc[i] += h[i][l + 1] * wv.y;
            acc[i] += h[i][l + 2] * wv.z;
            acc[i] += h[i][l + 3] * wv.w;
        }
    }
    const float bv = bl[a];
    #pragma unroll
    for (int i = 0; i < 8; i++) att2[(b0 + i) * ADIM + a] = acc[i] + bv;
}

// ---------------------------------------------------------------------------
// K2: fp16-split score GEMM.
//   main: a_hi.b_hi (f32 accum, full rate)
//   corr: (a_lo*2048).b_hi + a_hi.(b_lo*2048) (shared f16 accum, 2x rate)
// Grid (784, 2), 256 threads (8 warps), warp tile 32x64.
// ---------------------------------------------------------------------------
__global__ void __launch_bounds__(256, 1)
score_gemm_kernel(const float* __restrict__ A,      // conv_out, M x K
                  const float* __restrict__ bc,
                  const float* __restrict__ Wf,
                  const float* __restrict__ att2,   // B x 512
                  float* __restrict__ att_part)     // NBLK x M
{
    extern __shared__ char sm[];
    const uint32_t sb = smem_to_u32(sm);
    const int tid = threadIdx.x;
    const int lane = tid & 31;
    const int wid = tid >> 5;
    const int warp_m = wid >> 2;       // 0..1 (32 rows each)
    const int warp_n = wid & 3;        // 0..3 (64 cols each)
    const int bm = blockIdx.x;
    const int bn = blockIdx.y;
    const float* Ab = A + (size_t)bm * BM * CDIM;

    // ldmatrix per-lane offsets
    uint32_t aoff[2], boff[4];
    {
        const int ar = lane & 15, abyte = (lane >> 4) * 16;
        #pragma unroll
        for (int mb = 0; mb < 2; mb++)
            aoff[mb] = (uint32_t)((warp_m * 32 + mb * 16 + ar) * ROWB + abyte);
        const int bnr = (lane & 7) + ((lane >> 4) << 3);
        const int bbyte = ((lane >> 3) & 1) * 16;
        #pragma unroll
        for (int g = 0; g < 4; g++)
            boff[g] = (uint32_t)((warp_n * 64 + g * 16 + bnr) * ROWB + bbyte);
    }

    // A global: 64x16 fp32 per stage = 1024 floats -> 1 float4 per thread
    const int a_row = tid >> 2;        // 0..63
    const int a_c4  = tid & 3;
    const uint32_t a_soff = (uint32_t)(a_row * ROWB + a_c4 * 8);
    // B cp.async: 256 rows x 2 chunks x 2 splits = 1024 x 16B -> 4 per thread
    const int b_q   = tid & 1;
    const int b_row = tid >> 1;        // 0..127 (+128)

    float acc32[2][8][4];
    uint32_t acc16[2][8][2];
    #pragma unroll
    for (int mb = 0; mb < 2; mb++)
        #pragma unroll
        for (int nb = 0; nb < 8; nb++) {
            #pragma unroll
            for (int j = 0; j < 4; j++) acc32[mb][nb][j] = 0.f;
            acc16[mb][nb][0] = 0u; acc16[mb][nb][1] = 0u;
        }

    // ---- prologue: stage 0 -> buf 0 ----
    {
        float4 v = *reinterpret_cast<const float4*>(Ab + (size_t)a_row * CDIM + a_c4 * 4);
        __half h0 = __float2half(v.x), h1 = __float2half(v.y);
        __half h2 = __float2half(v.z), h3 = __float2half(v.w);
        __half l0 = __float2half((v.x - __half2float(h0)) * LOSCALE);
        __half l1 = __float2half((v.y - __half2float(h1)) * LOSCALE);
        __half l2 = __float2half((v.z - __half2float(h2)) * LOSCALE);
        __half l3 = __float2half((v.w - __half2float(h3)) * LOSCALE);
        *reinterpret_cast<uint2*>(sm + SM_A_HI(0) + a_soff) = make_uint2(pack_h(h0, h1), pack_h(h2, h3));
        *reinterpret_cast<uint2*>(sm + SM_A_LO(0) + a_soff) = make_uint2(pack_h(l0, l1), pack_h(l2, l3));
        #pragma unroll
        for (int i = 0; i < 2; i++) {
            const int r = b_row + i * 128;
            const size_t goff = (size_t)(bn * BN + r) * CDIM + b_q * 8;
            const uint32_t soff = (uint32_t)(r * ROWB + b_q * 16);
            CP_ASYNC16(sb + SM_B_HI(0) + soff, (const char*)(g_Wc_hi + goff));
            CP_ASYNC16(sb + SM_B_LO(0) + soff, (const char*)(g_Wc_lo + goff));
        }
        CP_COMMIT();
        CP_WAIT0();
    }
    __syncthreads();

    #pragma unroll 1
    for (int it = 0; it < NITER; it++) {
        const int buf = it & 1;
        const int nbf = buf ^ 1;
        const int k0 = (it + 1) * BK;
        float4 v;
        // issue next-stage loads
        if (it + 1 < NITER) {
            v = *reinterpret_cast<const float4*>(Ab + (size_t)a_row * CDIM + k0 + a_c4 * 4);
            #pragma unroll
            for (int i = 0; i < 2; i++) {
                const int r = b_row + i * 128;
                const size_t goff = (size_t)(bn * BN + r) * CDIM + k0 + b_q * 8;
                const uint32_t soff = (uint32_t)(r * ROWB + b_q * 16);
                CP_ASYNC16(sb + SM_B_HI(nbf) + soff, (const char*)(g_Wc_hi + goff));
                CP_ASYNC16(sb + SM_B_LO(nbf) + soff, (const char*)(g_Wc_lo + goff));
            }
            CP_COMMIT();
        }

        // ---- compute on buf ----
        uint32_t ah[2][4], al[2][4], bb[4][4];
        #pragma unroll
        for (int mb = 0; mb < 2; mb++) ldsm4(ah[mb], sb + SM_A_HI(buf) + aoff[mb]);
        #pragma unroll
        for (int mb = 0; mb < 2; mb++) ldsm4(al[mb], sb + SM_A_LO(buf) + aoff[mb]);
        #pragma unroll
        for (int g = 0; g < 4; g++) ldsm4(bb[g], sb + SM_B_HI(buf) + boff[g]);
        #pragma unroll
        for (int mb = 0; mb < 2; mb++)
            #pragma unroll
            for (int nb = 0; nb < 8; nb++)
                mma_f32(acc32[mb][nb], ah[mb], &bb[nb >> 1][(nb & 1) * 2]);
        #pragma unroll
        for (int mb = 0; mb < 2; mb++)
            #pragma unroll
            for (int nb = 0; nb < 8; nb++)
                mma_f16(acc16[mb][nb], al[mb], &bb[nb >> 1][(nb & 1) * 2]);
        #pragma unroll
        for (int g = 0; g < 4; g++) ldsm4(bb[g], sb + SM_B_LO(buf) + boff[g]);
        #pragma unroll
        for (int mb = 0; mb < 2; mb++)
            #pragma unroll
            for (int nb = 0; nb < 8; nb++)
                mma_f16(acc16[mb][nb], ah[mb], &bb[nb >> 1][(nb & 1) * 2]);

        // store next A stage (LDG latency hidden by compute above)
        if (it + 1 < NITER) {
            __half h0 = __float2half(v.x), h1 = __float2half(v.y);
            __half h2 = __float2half(v.z), h3 = __float2half(v.w);
            __half l0 = __float2half((v.x - __half2float(h0)) * LOSCALE);
            __half l1 = __float2half((v.y - __half2float(h1)) * LOSCALE);
            __half l2 = __float2half((v.z - __half2float(h2)) * LOSCALE);
            __half l3 = __float2half((v.w - __half2float(h3)) * LOSCALE);
            *reinterpret_cast<uint2*>(sm + SM_A_HI(nbf) + a_soff) = make_uint2(pack_h(h0, h1), pack_h(h2, h3));
            *reinterpret_cast<uint2*>(sm + SM_A_LO(nbf) + a_soff) = make_uint2(pack_h(l0, l1), pack_h(l2, l3));
            CP_WAIT0();
        }
        __syncthreads();
    }

    // ---- epilogue: score = acc32 + acc16/2048; relu(+bc+att2).Wf reduce ----
    float wfv[16], bcv[16];
    const int ncol0 = bn * BN + warp_n * 64;
    #pragma unroll
    for (int nb = 0; nb < 8; nb++)
        #pragma unroll
        for (int jj = 0; jj < 2; jj++) {
            const int n = ncol0 + nb * 8 + 2 * (lane & 3) + jj;
            wfv[nb * 2 + jj] = Wf[n];
            bcv[nb * 2 + jj] = bc[n];
        }

    float* red = reinterpret_cast<float*>(sm);   // [4][64]
    #pragma unroll
    for (int mb = 0; mb < 2; mb++) {
        #pragma unroll
        for (int half = 0; half < 2; half++) {
            const int m_loc = warp_m * 32 + mb * 16 + (lane >> 2) + half * 8;
            const int m = bm * BM + m_loc;
            const int b = m / NPIX;
            const float* a2 = att2 + (size_t)b * ADIM + ncol0;
            float s = 0.f;
            #pragma unroll
            for (int nb = 0; nb < 8; nb++) {
                float2 cf = __half22float2(*reinterpret_cast<__half2*>(&acc16[mb][nb][half]));
                #pragma unroll
                for (int jj = 0; jj < 2; jj++) {
                    const int ci = half * 2 + jj;
                    const int nrel = nb * 8 + 2 * (lane & 3) + jj;
                    float corr = (jj == 0 ? cf.x : cf.y) * (1.0f / LOSCALE);
                    float vv = acc32[mb][nb][ci] + corr + bcv[nb * 2 + jj] + a2[nrel];
                    s += fmaxf(vv, 0.f) * wfv[nb * 2 + jj];
                }
            }
            s += __shfl_xor_sync(0xFFFFFFFF, s, 1);
            s += __shfl_xor_sync(0xFFFFFFFF, s, 2);
            if ((lane & 3) == 0) red[warp_n * BM + m_loc] = s;
        }
    }
    __syncthreads();
    if (tid < BM) {
        float s = red[0 * BM + tid] + red[1 * BM + tid] + red[2 * BM + tid] + red[3 * BM + tid];
        att_part[(size_t)bn * MTOT + bm * BM + tid] = s;
    }
}

// ---------------------------------------------------------------------------
// K3: softmax over P=196 per batch row (2 partials).
// ---------------------------------------------------------------------------
__global__ void softmax_kernel(const float* __restrict__ att_part,
                               const float* __restrict__ bf,
                               float* __restrict__ alpha) {
    __shared__ float sv[256];
    const int b = blockIdx.x;
    const int tid = threadIdx.x;
    float val = 0.f;
    float v = -INFINITY;
    if (tid < NPIX) {
        const int m = b * NPIX + tid;
        val = bf[0] + att_part[0 * MTOT + m] + att_part[1 * MTOT + m];
        v = val;
    }
    sv[tid] = v;
    __syncthreads();
    #pragma unroll
    for (int s = 128; s > 0; s >>= 1) {
        if (tid < s) sv[tid] = fmaxf(sv[tid], sv[tid + s]);
        __syncthreads();
    }
    const float mx = sv[0];
    __syncthreads();
    const float e = (tid < NPIX) ? expf(val - mx) : 0.f;
    sv[tid] = e;
    __syncthreads();
    #pragma unroll
    for (int s = 128; s > 0; s >>= 1) {
        if (tid < s) sv[tid] = sv[tid] + sv[tid + s];
        __syncthreads();
    }
    const float sum = sv[0];
    if (tid < NPIX) alpha[b * NPIX + tid] = e / sum;
}

// ---------------------------------------------------------------------------
// K4: out[b][c] = sum_p conv[b][p][c] * alpha[b][p]  (float4, 2 chains)
// ---------------------------------------------------------------------------
__global__ void pool_kernel(const float* __restrict__ conv,
                            const float* __restrict__ alpha,
                            float* __restrict__ out) {
    __shared__ float al[NPIX];
    const int b = blockIdx.y;
    const int c4 = blockIdx.x * 256 + threadIdx.x;
    if (threadIdx.x < NPIX) al[threadIdx.x] = alpha[b * NPIX + threadIdx.x];
    __syncthreads();
    const float4* cp = reinterpret_cast<const float4*>(conv + (size_t)b * NPIX * CDIM) + c4;
    float4 a0 = make_float4(0.f, 0.f, 0.f, 0.f);
    float4 a1 = make_float4(0.f, 0.f, 0.f, 0.f);
    #pragma unroll 4
    for (int p = 0; p < NPIX; p += 2) {
        float4 v0 = cp[(size_t)p * (CDIM / 4)];
        float4 v1 = cp[(size_t)(p + 1) * (CDIM / 4)];
        float w0 = al[p], w1 = al[p + 1];
        a0.x += v0.x * w0; a0.y += v0.y * w0; a0.z += v0.z * w0; a0.w += v0.w * w0;
        a1.x += v1.x * w1; a1.y += v1.y * w1; a1.z += v1.z * w1; a1.w += v1.w * w1;
    }
    float4 r = make_float4(a0.x + a1.x, a0.y + a1.y, a0.z + a1.z, a0.w + a1.w);
    reinterpret_cast<float4*>(out)[(size_t)b * (CDIM / 4) + c4] = r;
}

// ---------------------------------------------------------------------------
extern "C" void kernel_launch(void* const* d_in, const int* in_sizes, int n_in,
                              void* d_out, int out_size) {
    const float* conv = (const float*)d_in[0];
    const float* lstm = (const float*)d_in[1];
    const float* Wc   = (const float*)d_in[2];
    const float* bc   = (const float*)d_in[3];
    const float* Wl   = (const float*)d_in[4];
    const float* bl   = (const float*)d_in[5];
    const float* Wf   = (const float*)d_in[6];
    const float* bf   = (const float*)d_in[7];
    float* out = (float*)d_out;

    float* att2;     cudaGetSymbolAddress((void**)&att2, g_att2);
    float* att_part; cudaGetSymbolAddress((void**)&att_part, g_att_part);
    float* alpha;    cudaGetSymbolAddress((void**)&alpha, g_alpha);

    cudaFuncSetAttribute(score_gemm_kernel,
                         cudaFuncAttributeMaxDynamicSharedMemorySize, SMEM_BYTES);

    convert_wc_kernel<<<(ADIM * CDIM / 4) / 256, 256>>>(Wc);
    att2_kernel<<<BATCH / 8, LDIM>>>(lstm, Wl, bl, att2);

    dim3 gg(MTOT / BM, NBLK);
    score_gemm_kernel<<<gg, 256, SMEM_BYTES>>>(conv, bc, Wf, att2, att_part);

    softmax_kernel<<<BATCH, 256>>>(att_part, bf, alpha);
    pool_kernel<<<dim3(CDIM / 4 / 256, BATCH), 256>>>(conv, alpha, out);
}

// round 8
// speedup vs baseline: 1.1818x; 1.1818x over previous
#include <cuda_runtime.h>
#include <cuda_bf16.h>
#include <math.h>
#include <stdint.h>

// Problem dims (fixed by the reference)
#define BATCH 256
#define NPIX  196
#define CDIM  2048
#define ADIM  512
#define LDIM  512
#define MTOT  (BATCH * NPIX)   // 50176 = 392 * 128

// GEMM tiling (mma.sync m16n8k16)
#define BM 128
#define BN 256
#define BK 16
#define NBLK (ADIM / BN)       // 2
#define NITER (CDIM / BK)      // 128
#define WM 64
#define WN 64
#define NSTAGE 3

// Scratch (device globals — no allocation allowed)
__device__ float g_att2[BATCH * ADIM];
__device__ float g_att_part[NBLK * MTOT];
__device__ float g_alpha[MTOT];
__device__ __nv_bfloat16 g_Wc_hi[ADIM * CDIM];
__device__ __nv_bfloat16 g_Wc_lo[ADIM * CDIM];
__device__ __nv_bfloat16 g_A_hi[(size_t)MTOT * CDIM];   // 205.5 MB
__device__ __nv_bfloat16 g_A_lo[(size_t)MTOT * CDIM];   // 205.5 MB

// smem: row stride 48B (16 bf16 + 8B pad) — conflict-free LDSM
#define ROWB 48
#define BUFSZ 36864
#define SM_A_HI(b) ((b) * BUFSZ + 0)
#define SM_A_LO(b) ((b) * BUFSZ + 6144)
#define SM_B_HI(b) ((b) * BUFSZ + 12288)
#define SM_B_LO(b) ((b) * BUFSZ + 24576)
#define SMEM_BYTES (NSTAGE * BUFSZ)

__device__ __forceinline__ uint32_t smem_to_u32(const void* p) {
    uint32_t a;
    asm("{ .reg .u64 t; cvta.to.shared.u64 t, %1; cvt.u32.u64 %0, t; }" : "=r"(a) : "l"(p));
    return a;
}
__device__ __forceinline__ void ldsm4(uint32_t* r, uint32_t addr) {
    asm volatile("ldmatrix.sync.aligned.m8n8.x4.shared.b16 {%0,%1,%2,%3}, [%4];"
                 : "=r"(r[0]), "=r"(r[1]), "=r"(r[2]), "=r"(r[3]) : "r"(addr));
}
__device__ __forceinline__ void mma16816(float* c, const uint32_t* a, const uint32_t* b) {
    asm volatile("mma.sync.aligned.m16n8k16.row.col.f32.bf16.bf16.f32 "
                 "{%0,%1,%2,%3}, {%4,%5,%6,%7}, {%8,%9}, {%0,%1,%2,%3};"
                 : "+f"(c[0]), "+f"(c[1]), "+f"(c[2]), "+f"(c[3])
                 : "r"(a[0]), "r"(a[1]), "r"(a[2]), "r"(a[3]), "r"(b[0]), "r"(b[1]));
}
#define CP_ASYNC16(dst, src) \
    asm volatile("cp.async.cg.shared.global [%0], [%1], 16;" :: "r"(dst), "l"(src))
#define CP_COMMIT() asm volatile("cp.async.commit_group;" ::: "memory")
#define CP_WAIT1()  asm volatile("cp.async.wait_group 1;" ::: "memory")
#define CP_WAIT0()  asm volatile("cp.async.wait_group 0;" ::: "memory")

__device__ __forceinline__ uint32_t pack_bf16(__nv_bfloat16 a, __nv_bfloat16 b) {
    return (uint32_t)__bfloat16_as_ushort(a) | ((uint32_t)__bfloat16_as_ushort(b) << 16);
}

// ---------------------------------------------------------------------------
// K0a: convert Wc -> bf16 hi/lo
// ---------------------------------------------------------------------------
__global__ void convert_wc_kernel(const float* __restrict__ Wc) {
    const size_t i4 = (size_t)blockIdx.x * 256 + threadIdx.x;
    float4 v = reinterpret_cast<const float4*>(Wc)[i4];
    __nv_bfloat16 h0 = __float2bfloat16(v.x), h1 = __float2bfloat16(v.y);
    __nv_bfloat16 h2 = __float2bfloat16(v.z), h3 = __float2bfloat16(v.w);
    __nv_bfloat16 l0 = __float2bfloat16(v.x - __bfloat162float(h0));
    __nv_bfloat16 l1 = __float2bfloat16(v.y - __bfloat162float(h1));
    __nv_bfloat16 l2 = __float2bfloat16(v.z - __bfloat162float(h2));
    __nv_bfloat16 l3 = __float2bfloat16(v.w - __bfloat162float(h3));
    reinterpret_cast<uint2*>(g_Wc_hi)[i4] = make_uint2(pack_bf16(h0, h1), pack_bf16(h2, h3));
    reinterpret_cast<uint2*>(g_Wc_lo)[i4] = make_uint2(pack_bf16(l0, l1), pack_bf16(l2, l3));
}

// ---------------------------------------------------------------------------
// K0b: convert conv_out -> bf16 hi/lo  (102.7M elements)
// ---------------------------------------------------------------------------
__global__ void convert_a_kernel(const float* __restrict__ A) {
    const size_t i4 = (size_t)blockIdx.x * 256 + threadIdx.x;
    float4 v = reinterpret_cast<const float4*>(A)[i4];
    __nv_bfloat16 h0 = __float2bfloat16(v.x), h1 = __float2bfloat16(v.y);
    __nv_bfloat16 h2 = __float2bfloat16(v.z), h3 = __float2bfloat16(v.w);
    __nv_bfloat16 l0 = __float2bfloat16(v.x - __bfloat162float(h0));
    __nv_bfloat16 l1 = __float2bfloat16(v.y - __bfloat162float(h1));
    __nv_bfloat16 l2 = __float2bfloat16(v.z - __bfloat162float(h2));
    __nv_bfloat16 l3 = __float2bfloat16(v.w - __bfloat162float(h3));
    reinterpret_cast<uint2*>(g_A_hi)[i4] = make_uint2(pack_bf16(h0, h1), pack_bf16(h2, h3));
    reinterpret_cast<uint2*>(g_A_lo)[i4] = make_uint2(pack_bf16(l0, l1), pack_bf16(l2, l3));
}

// ---------------------------------------------------------------------------
// K1: att2[b][a] = lstm[b] . Wl[a] + bl[a]
// ---------------------------------------------------------------------------
__global__ void att2_kernel(const float* __restrict__ lstm,
                            const float* __restrict__ Wl,
                            const float* __restrict__ bl,
                            float* __restrict__ att2) {
    __shared__ float h[8][LDIM];
    const int b0 = blockIdx.x * 8;
    const int a = threadIdx.x;
    #pragma unroll
    for (int i = 0; i < 8; i++) h[i][a] = lstm[(b0 + i) * LDIM + a];
    __syncthreads();
    const float4* w4 = reinterpret_cast<const float4*>(Wl + (size_t)a * LDIM);
    float acc[8] = {0.f, 0.f, 0.f, 0.f, 0.f, 0.f, 0.f, 0.f};
    #pragma unroll 4
    for (int l4 = 0; l4 < LDIM / 4; l4++) {
        float4 wv = w4[l4];
        int l = l4 * 4;
        #pragma unroll
        for (int i = 0; i < 8; i++) {
            acc[i] += h[i][l + 0] * wv.x;
            acc[i] += h[i][l + 1] * wv.y;
            acc[i] += h[i][l + 2] * wv.z;
            acc[i] += h[i][l + 3] * wv.w;
        }
    }
    const float bv = bl[a];
    #pragma unroll
    for (int i = 0; i < 8; i++) att2[(b0 + i) * ADIM + a] = acc[i] + bv;
}

// ---------------------------------------------------------------------------
// K2: bf16-split-3 score GEMM, pure cp.async 3-stage pipeline.
// Grid (392, 2), 256 threads (8 warps 2x4), warp tile 64x64.
// ---------------------------------------------------------------------------
__global__ void __launch_bounds__(256, 1)
score_gemm_kernel(const float* __restrict__ bc,
                  const float* __restrict__ Wf,
                  const float* __restrict__ att2,   // B x 512
                  float* __restrict__ att_part)     // NBLK x M
{
    extern __shared__ char sm[];
    const uint32_t sb = smem_to_u32(sm);
    const int tid = threadIdx.x;
    const int lane = tid & 31;
    const int wid = tid >> 5;
    const int warp_m = wid >> 2;       // 0..1
    const int warp_n = wid & 3;        // 0..3
    const int bm = blockIdx.x;
    const int bn = blockIdx.y;

    // ldmatrix per-lane offsets
    uint32_t aoff[4], boff[4];
    {
        const int ar = lane & 15, abyte = (lane >> 4) * 16;
        #pragma unroll
        for (int mb = 0; mb < 4; mb++)
            aoff[mb] = (uint32_t)((warp_m * WM + mb * 16 + ar) * ROWB + abyte);
        const int bnr = (lane & 7) + ((lane >> 4) << 3);
        const int bbyte = ((lane >> 3) & 1) * 16;
        #pragma unroll
        for (int g = 0; g < 4; g++)
            boff[g] = (uint32_t)((warp_n * WN + g * 16 + bnr) * ROWB + bbyte);
    }

    // cp.async chunk assignment:
    //   A: 128 rows x 2 chunks (16B) per split -> tid covers both (row=tid>>1, q=tid&1)
    //   B: 256 rows x 2 chunks per split -> tid, tid+256
    const int a_row = tid >> 1, a_q = tid & 1;
    const uint32_t a_soff = (uint32_t)(a_row * ROWB + a_q * 16);
    const size_t a_goff0 = (size_t)(bm * BM + a_row) * CDIM + a_q * 8;
    const int b_row = tid >> 1, b_q = tid & 1;
    const uint32_t b_soff0 = (uint32_t)(b_row * ROWB + b_q * 16);
    const uint32_t b_soff1 = (uint32_t)((b_row + 128) * ROWB + b_q * 16);
    const size_t b_goff0 = (size_t)(bn * BN + b_row) * CDIM + b_q * 8;
    const size_t b_goff1 = (size_t)(bn * BN + b_row + 128) * CDIM + b_q * 8;

    float acc[4][8][4];
    #pragma unroll
    for (int mb = 0; mb < 4; mb++)
        #pragma unroll
        for (int nb = 0; nb < 8; nb++)
            #pragma unroll
            for (int j = 0; j < 4; j++) acc[mb][nb][j] = 0.f;

    // issue stage s loads into buffer s%NSTAGE
    auto issue = [&](int s) {
        const int buf = s % NSTAGE;
        const int k0 = s * BK;
        CP_ASYNC16(sb + SM_A_HI(buf) + a_soff, (const char*)(g_A_hi + a_goff0 + k0));
        CP_ASYNC16(sb + SM_A_LO(buf) + a_soff, (const char*)(g_A_lo + a_goff0 + k0));
        CP_ASYNC16(sb + SM_B_HI(buf) + b_soff0, (const char*)(g_Wc_hi + b_goff0 + k0));
        CP_ASYNC16(sb + SM_B_HI(buf) + b_soff1, (const char*)(g_Wc_hi + b_goff1 + k0));
        CP_ASYNC16(sb + SM_B_LO(buf) + b_soff0, (const char*)(g_Wc_lo + b_goff0 + k0));
        CP_ASYNC16(sb + SM_B_LO(buf) + b_soff1, (const char*)(g_Wc_lo + b_goff1 + k0));
        CP_COMMIT();
    };

    issue(0);
    issue(1);
    CP_WAIT1();          // stage 0 complete
    __syncthreads();

    #pragma unroll 1
    for (int it = 0; it < NITER; it++) {
        const int buf = it % NSTAGE;
        if (it + 2 < NITER) issue(it + 2);

        uint32_t ah[4][4], al[4][4], bb[4][4];
        #pragma unroll
        for (int mb = 0; mb < 4; mb++) ldsm4(ah[mb], sb + SM_A_HI(buf) + aoff[mb]);
        #pragma unroll
        for (int g = 0; g < 4; g++) ldsm4(bb[g], sb + SM_B_HI(buf) + boff[g]);
        #pragma unroll
        for (int mb = 0; mb < 4; mb++)
            #pragma unroll
            for (int nb = 0; nb < 8; nb++)
                mma16816(acc[mb][nb], ah[mb], &bb[nb >> 1][(nb & 1) * 2]);
        #pragma unroll
        for (int mb = 0; mb < 4; mb++) ldsm4(al[mb], sb + SM_A_LO(buf) + aoff[mb]);
        #pragma unroll
        for (int mb = 0; mb < 4; mb++)
            #pragma unroll
            for (int nb = 0; nb < 8; nb++)
                mma16816(acc[mb][nb], al[mb], &bb[nb >> 1][(nb & 1) * 2]);
        #pragma unroll
        for (int g = 0; g < 4; g++) ldsm4(bb[g], sb + SM_B_LO(buf) + boff[g]);
        #pragma unroll
        for (int mb = 0; mb < 4; mb++)
            #pragma unroll
            for (int nb = 0; nb < 8; nb++)
                mma16816(acc[mb][nb], ah[mb], &bb[nb >> 1][(nb & 1) * 2]);

        if (it + 2 < NITER) CP_WAIT1();
        else CP_WAIT0();
        __syncthreads();
    }

    // ---- epilogue: relu(C + bc + att2) . Wf reduced over n ----
    float wfv[16], bcv[16];
    const int ncol0 = bn * BN + warp_n * WN;
    #pragma unroll
    for (int nb = 0; nb < 8; nb++)
        #pragma unroll
        for (int jj = 0; jj < 2; jj++) {
            const int n = ncol0 + nb * 8 + 2 * (lane & 3) + jj;
            wfv[nb * 2 + jj] = Wf[n];
            bcv[nb * 2 + jj] = bc[n];
        }

    float* red = reinterpret_cast<float*>(sm);   // [4][128]
    #pragma unroll
    for (int mb = 0; mb < 4; mb++) {
        #pragma unroll
        for (int half = 0; half < 2; half++) {
            const int m_loc = warp_m * WM + mb * 16 + (lane >> 2) + half * 8;
            const int m = bm * BM + m_loc;
            const int b = m / NPIX;
            const float* a2 = att2 + (size_t)b * ADIM + ncol0;
            float s = 0.f;
            #pragma unroll
            for (int nb = 0; nb < 8; nb++)
                #pragma unroll
                for (int jj = 0; jj < 2; jj++) {
                    const int ci = half * 2 + jj;
                    const int nrel = nb * 8 + 2 * (lane & 3) + jj;
                    float v = acc[mb][nb][ci] + bcv[nb * 2 + jj] + a2[nrel];
                    s += fmaxf(v, 0.f) * wfv[nb * 2 + jj];
                }
            s += __shfl_xor_sync(0xFFFFFFFF, s, 1);
            s += __shfl_xor_sync(0xFFFFFFFF, s, 2);
            if ((lane & 3) == 0) red[warp_n * BM + m_loc] = s;
        }
    }
    __syncthreads();
    if (tid < BM) {
        float s = red[0 * BM + tid] + red[1 * BM + tid] + red[2 * BM + tid] + red[3 * BM + tid];
        att_part[(size_t)bn * MTOT + bm * BM + tid] = s;
    }
}

// ---------------------------------------------------------------------------
// K3: softmax over P=196 per batch row (2 partials).
// ---------------------------------------------------------------------------
__global__ void softmax_kernel(const float* __restrict__ att_part,
                               const float* __restrict__ bf,
                               float* __restrict__ alpha) {
    __shared__ float sv[256];
    const int b = blockIdx.x;
    const int tid = threadIdx.x;
    float val = 0.f;
    float v = -INFINITY;
    if (tid < NPIX) {
        const int m = b * NPIX + tid;
        val = bf[0] + att_part[0 * MTOT + m] + att_part[1 * MTOT + m];
        v = val;
    }
    sv[tid] = v;
    __syncthreads();
    #pragma unroll
    for (int s = 128; s > 0; s >>= 1) {
        if (tid < s) sv[tid] = fmaxf(sv[tid], sv[tid + s]);
        __syncthreads();
    }
    const float mx = sv[0];
    __syncthreads();
    const float e = (tid < NPIX) ? expf(val - mx) : 0.f;
    sv[tid] = e;
    __syncthreads();
    #pragma unroll
    for (int s = 128; s > 0; s >>= 1) {
        if (tid < s) sv[tid] = sv[tid] + sv[tid + s];
        __syncthreads();
    }
    const float sum = sv[0];
    if (tid < NPIX) alpha[b * NPIX + tid] = e / sum;
}

// ---------------------------------------------------------------------------
// K4: out[b][c] = sum_p conv[b][p][c] * alpha[b][p]  (float4, 2 chains)
// ---------------------------------------------------------------------------
__global__ void pool_kernel(const float* __restrict__ conv,
                            const float* __restrict__ alpha,
                            float* __restrict__ out) {
    __shared__ float al[NPIX];
    const int b = blockIdx.y;
    const int c4 = blockIdx.x * 256 + threadIdx.x;
    if (threadIdx.x < NPIX) al[threadIdx.x] = alpha[b * NPIX + threadIdx.x];
    __syncthreads();
    const float4* cp = reinterpret_cast<const float4*>(conv + (size_t)b * NPIX * CDIM) + c4;
    float4 a0 = make_float4(0.f, 0.f, 0.f, 0.f);
    float4 a1 = make_float4(0.f, 0.f, 0.f, 0.f);
    #pragma unroll 4
    for (int p = 0; p < NPIX; p += 2) {
        float4 v0 = cp[(size_t)p * (CDIM / 4)];
        float4 v1 = cp[(size_t)(p + 1) * (CDIM / 4)];
        float w0 = al[p], w1 = al[p + 1];
        a0.x += v0.x * w0; a0.y += v0.y * w0; a0.z += v0.z * w0; a0.w += v0.w * w0;
        a1.x += v1.x * w1; a1.y += v1.y * w1; a1.z += v1.z * w1; a1.w += v1.w * w1;
    }
    float4 r = make_float4(a0.x + a1.x, a0.y + a1.y, a0.z + a1.z, a0.w + a1.w);
    reinterpret_cast<float4*>(out)[(size_t)b * (CDIM / 4) + c4] = r;
}

// ---------------------------------------------------------------------------
extern "C" void kernel_launch(void* const* d_in, const int* in_sizes, int n_in,
                              void* d_out, int out_size) {
    const float* conv = (const float*)d_in[0];
    const float* lstm = (const float*)d_in[1];
    const float* Wc   = (const float*)d_in[2];
    const float* bc   = (const float*)d_in[3];
    const float* Wl   = (const float*)d_in[4];
    const float* bl   = (const float*)d_in[5];
    const float* Wf   = (const float*)d_in[6];
    const float* bf   = (const float*)d_in[7];
    float* out = (float*)d_out;

    float* att2;     cudaGetSymbolAddress((void**)&att2, g_att2);
    float* att_part; cudaGetSymbolAddress((void**)&att_part, g_att_part);
    float* alpha;    cudaGetSymbolAddress((void**)&alpha, g_alpha);

    cudaFuncSetAttribute(score_gemm_kernel,
                         cudaFuncAttributeMaxDynamicSharedMemorySize, SMEM_BYTES);

    convert_wc_kernel<<<(ADIM * CDIM / 4) / 256, 256>>>(Wc);
    convert_a_kernel<<<(int)(((size_t)MTOT * CDIM / 4) / 256), 256>>>(conv);
    att2_kernel<<<BATCH / 8, LDIM>>>(lstm, Wl, bl, att2);

    dim3 gg(MTOT / BM, NBLK);
    score_gemm_kernel<<<gg, 256, SMEM_BYTES>>>(bc, Wf, att2, att_part);

    softmax_kernel<<<BATCH, 256>>>(att_part, bf, alpha);
    pool_kernel<<<dim3(CDIM / 4 / 256, BATCH), 256>>>(conv, alpha, out);
}

// round 9
// speedup vs baseline: 1.8280x; 1.5468x over previous
#include <cuda_runtime.h>
#include <cuda_fp16.h>
#include <math.h>
#include <stdint.h>

// Problem dims (fixed by the reference)
#define BATCH 256
#define NPIX  196
#define CDIM  2048
#define ADIM  512
#define LDIM  512
#define MTOT  (BATCH * NPIX)   // 50176 = 392 * 128

// GEMM tiling (mma.sync m16n8k16, fp16 in / f32 accum)
#define BM 128
#define BN 128
#define BK 16
#define NBLK (ADIM / BN)       // 4
#define NITER (CDIM / BK)      // 128
#define WM 64
#define WN 32
#define NSTAGE 4

// Scratch (device globals — no allocation allowed)
__device__ float g_att2[BATCH * ADIM];
__device__ float g_att_part[NBLK * MTOT];
__device__ float g_alpha[MTOT];
__device__ __half g_Wc_h[ADIM * CDIM];                 // fp16(Wc)
__device__ __half g_A_hi[(size_t)MTOT * CDIM];         // fp16(A)
__device__ __half g_A_lo[(size_t)MTOT * CDIM];         // fp16(A - hi), unscaled

// smem: row stride 48B (16 fp16 + 8B pad) — conflict-free LDSM
#define ROWB 48
#define TILEB (128 * ROWB)     // 6144
#define SM_A_HI(s) ((s) * (3 * TILEB) + 0)
#define SM_A_LO(s) ((s) * (3 * TILEB) + TILEB)
#define SM_B(s)    ((s) * (3 * TILEB) + 2 * TILEB)
#define SMEM_BYTES (NSTAGE * 3 * TILEB)   // 73728

__device__ __forceinline__ uint32_t smem_to_u32(const void* p) {
    uint32_t a;
    asm("{ .reg .u64 t; cvta.to.shared.u64 t, %1; cvt.u32.u64 %0, t; }" : "=r"(a) : "l"(p));
    return a;
}
__device__ __forceinline__ void ldsm4(uint32_t* r, uint32_t addr) {
    asm volatile("ldmatrix.sync.aligned.m8n8.x4.shared.b16 {%0,%1,%2,%3}, [%4];"
                 : "=r"(r[0]), "=r"(r[1]), "=r"(r[2]), "=r"(r[3]) : "r"(addr));
}
__device__ __forceinline__ void mma16816(float* c, const uint32_t* a, const uint32_t* b) {
    asm volatile("mma.sync.aligned.m16n8k16.row.col.f32.f16.f16.f32 "
                 "{%0,%1,%2,%3}, {%4,%5,%6,%7}, {%8,%9}, {%0,%1,%2,%3};"
                 : "+f"(c[0]), "+f"(c[1]), "+f"(c[2]), "+f"(c[3])
                 : "r"(a[0]), "r"(a[1]), "r"(a[2]), "r"(a[3]), "r"(b[0]), "r"(b[1]));
}
#define CP_ASYNC16(dst, src) \
    asm volatile("cp.async.cg.shared.global [%0], [%1], 16;" :: "r"(dst), "l"(src))
#define CP_COMMIT() asm volatile("cp.async.commit_group;" ::: "memory")
#define CP_WAIT2()  asm volatile("cp.async.wait_group 2;" ::: "memory")
#define CP_WAIT0()  asm volatile("cp.async.wait_group 0;" ::: "memory")

__device__ __forceinline__ uint32_t pack_h(__half a, __half b) {
    return (uint32_t)__half_as_ushort(a) | ((uint32_t)__half_as_ushort(b) << 16);
}

// ---------------------------------------------------------------------------
// K0a: convert Wc -> fp16 (single rounding)
// ---------------------------------------------------------------------------
__global__ void convert_wc_kernel(const float* __restrict__ Wc) {
    const size_t i4 = (size_t)blockIdx.x * 256 + threadIdx.x;
    float4 v = reinterpret_cast<const float4*>(Wc)[i4];
    __half h0 = __float2half(v.x), h1 = __float2half(v.y);
    __half h2 = __float2half(v.z), h3 = __float2half(v.w);
    reinterpret_cast<uint2*>(g_Wc_h)[i4] = make_uint2(pack_h(h0, h1), pack_h(h2, h3));
}

// ---------------------------------------------------------------------------
// K0b: convert conv_out -> fp16 double-half (hi + residual lo)
// ---------------------------------------------------------------------------
__global__ void convert_a_kernel(const float* __restrict__ A) {
    const size_t i4 = (size_t)blockIdx.x * 256 + threadIdx.x;
    float4 v = reinterpret_cast<const float4*>(A)[i4];
    __half h0 = __float2half(v.x), h1 = __float2half(v.y);
    __half h2 = __float2half(v.z), h3 = __float2half(v.w);
    __half l0 = __float2half(v.x - __half2float(h0));
    __half l1 = __float2half(v.y - __half2float(h1));
    __half l2 = __float2half(v.z - __half2float(h2));
    __half l3 = __float2half(v.w - __half2float(h3));
    reinterpret_cast<uint2*>(g_A_hi)[i4] = make_uint2(pack_h(h0, h1), pack_h(h2, h3));
    reinterpret_cast<uint2*>(g_A_lo)[i4] = make_uint2(pack_h(l0, l1), pack_h(l2, l3));
}

// ---------------------------------------------------------------------------
// K1: att2[b][a] = lstm[b] . Wl[a] + bl[a]
// ---------------------------------------------------------------------------
__global__ void att2_kernel(const float* __restrict__ lstm,
                            const float* __restrict__ Wl,
                            const float* __restrict__ bl,
                            float* __restrict__ att2) {
    __shared__ float h[8][LDIM];
    const int b0 = blockIdx.x * 8;
    const int a = threadIdx.x;
    #pragma unroll
    for (int i = 0; i < 8; i++) h[i][a] = lstm[(b0 + i) * LDIM + a];
    __syncthreads();
    const float4* w4 = reinterpret_cast<const float4*>(Wl + (size_t)a * LDIM);
    float acc[8] = {0.f, 0.f, 0.f, 0.f, 0.f, 0.f, 0.f, 0.f};
    #pragma unroll 4
    for (int l4 = 0; l4 < LDIM / 4; l4++) {
        float4 wv = w4[l4];
        int l = l4 * 4;
        #pragma unroll
        for (int i = 0; i < 8; i++) {
            acc[i] += h[i][l + 0] * wv.x;
            acc[i] += h[i][l + 1] * wv.y;
            acc[i] += h[i][l + 2] * wv.z;
            acc[i] += h[i][l + 3] * wv.w;
        }
    }
    const float bv = bl[a];
    #pragma unroll
    for (int i = 0; i < 8; i++) att2[(b0 + i) * ADIM + a] = acc[i] + bv;
}

// ---------------------------------------------------------------------------
// K2: fp16 double-half score GEMM, 4-stage cp.async, 2 CTAs/SM.
// Grid (4, 392): bn fast => 4 CTAs share one A tile via L2.
// 256 threads (8 warps 2x4), warp tile 64x32, acc 64 f32/thread.
// ---------------------------------------------------------------------------
__global__ void __launch_bounds__(256, 2)
score_gemm_kernel(const float* __restrict__ bc,
                  const float* __restrict__ Wf,
                  const float* __restrict__ att2,   // B x 512
                  float* __restrict__ att_part)     // NBLK x M
{
    extern __shared__ char sm[];
    const uint32_t sb = smem_to_u32(sm);
    const int tid = threadIdx.x;
    const int lane = tid & 31;
    const int wid = tid >> 5;
    const int warp_m = wid >> 2;       // 0..1
    const int warp_n = wid & 3;        // 0..3
    const int bn = blockIdx.x;         // 0..3  (fast: A-tile L2 sharing)
    const int bm = blockIdx.y;         // 0..391

    // ldmatrix per-lane offsets
    uint32_t aoff[4], boff[2];
    {
        const int ar = lane & 15, abyte = (lane >> 4) * 16;
        #pragma unroll
        for (int mb = 0; mb < 4; mb++)
            aoff[mb] = (uint32_t)((warp_m * WM + mb * 16 + ar) * ROWB + abyte);
        const int bnr = (lane & 7) + ((lane >> 4) << 3);
        const int bbyte = ((lane >> 3) & 1) * 16;
        #pragma unroll
        for (int g = 0; g < 2; g++)
            boff[g] = (uint32_t)((warp_n * WN + g * 16 + bnr) * ROWB + bbyte);
    }

    // cp.async: 128 rows x 2 chunks (16B) per matrix -> 1 chunk/thread/matrix
    const int c_row = tid >> 1, c_q = tid & 1;
    const uint32_t c_soff = (uint32_t)(c_row * ROWB + c_q * 16);
    const size_t a_goff = (size_t)(bm * BM + c_row) * CDIM + c_q * 8;
    const size_t b_goff = (size_t)(bn * BN + c_row) * CDIM + c_q * 8;

    float acc[4][4][4];
    #pragma unroll
    for (int mb = 0; mb < 4; mb++)
        #pragma unroll
        for (int nb = 0; nb < 4; nb++)
            #pragma unroll
            for (int j = 0; j < 4; j++) acc[mb][nb][j] = 0.f;

    auto issue = [&](int s) {
        const int buf = s & (NSTAGE - 1);
        const int k0 = s * BK;
        CP_ASYNC16(sb + SM_A_HI(buf) + c_soff, (const char*)(g_A_hi + a_goff + k0));
        CP_ASYNC16(sb + SM_A_LO(buf) + c_soff, (const char*)(g_A_lo + a_goff + k0));
        CP_ASYNC16(sb + SM_B(buf)    + c_soff, (const char*)(g_Wc_h + b_goff + k0));
        CP_COMMIT();
    };

    issue(0); issue(1); issue(2);
    CP_WAIT2();            // stage 0 complete
    __syncthreads();

    #pragma unroll 1
    for (int it = 0; it < NITER; it++) {
        const int buf = it & (NSTAGE - 1);
        const bool more = (it + 3 < NITER);
        if (more) issue(it + 3);

        uint32_t a[4][4], b[2][4];
        #pragma unroll
        for (int g = 0; g < 2; g++) ldsm4(b[g], sb + SM_B(buf) + boff[g]);
        #pragma unroll
        for (int mb = 0; mb < 4; mb++) ldsm4(a[mb], sb + SM_A_HI(buf) + aoff[mb]);
        #pragma unroll
        for (int mb = 0; mb < 4; mb++)
            #pragma unroll
            for (int nb = 0; nb < 4; nb++)
                mma16816(acc[mb][nb], a[mb], &b[nb >> 1][(nb & 1) * 2]);
        #pragma unroll
        for (int mb = 0; mb < 4; mb++) ldsm4(a[mb], sb + SM_A_LO(buf) + aoff[mb]);
        #pragma unroll
        for (int mb = 0; mb < 4; mb++)
            #pragma unroll
            for (int nb = 0; nb < 4; nb++)
                mma16816(acc[mb][nb], a[mb], &b[nb >> 1][(nb & 1) * 2]);

        if (more) { CP_WAIT2(); } else { CP_WAIT0(); }
        __syncthreads();
    }

    // ---- epilogue: relu(C + bc + att2) . Wf reduced over n ----
    float wfv[8], bcv[8];
    const int ncol0 = bn * BN + warp_n * WN;
    #pragma unroll
    for (int nb = 0; nb < 4; nb++)
        #pragma unroll
        for (int jj = 0; jj < 2; jj++) {
            const int n = ncol0 + nb * 8 + 2 * (lane & 3) + jj;
            wfv[nb * 2 + jj] = Wf[n];
            bcv[nb * 2 + jj] = bc[n];
        }

    float* red = reinterpret_cast<float*>(sm);   // [4][128]
    #pragma unroll
    for (int mb = 0; mb < 4; mb++) {
        #pragma unroll
        for (int half = 0; half < 2; half++) {
            const int m_loc = warp_m * WM + mb * 16 + (lane >> 2) + half * 8;
            const int m = bm * BM + m_loc;
            const int b = m / NPIX;
            const float* a2 = att2 + (size_t)b * ADIM + ncol0;
            float s = 0.f;
            #pragma unroll
            for (int nb = 0; nb < 4; nb++)
                #pragma unroll
                for (int jj = 0; jj < 2; jj++) {
                    const int ci = half * 2 + jj;
                    const int nrel = nb * 8 + 2 * (lane & 3) + jj;
                    float v = acc[mb][nb][ci] + bcv[nb * 2 + jj] + a2[nrel];
                    s += fmaxf(v, 0.f) * wfv[nb * 2 + jj];
                }
            s += __shfl_xor_sync(0xFFFFFFFF, s, 1);
            s += __shfl_xor_sync(0xFFFFFFFF, s, 2);
            if ((lane & 3) == 0) red[warp_n * BM + m_loc] = s;
        }
    }
    __syncthreads();
    if (tid < BM) {
        float s = red[0 * BM + tid] + red[1 * BM + tid] + red[2 * BM + tid] + red[3 * BM + tid];
        att_part[(size_t)bn * MTOT + bm * BM + tid] = s;
    }
}

// ---------------------------------------------------------------------------
// K3: softmax over P=196 per batch row (4 partials).
// ---------------------------------------------------------------------------
__global__ void softmax_kernel(const float* __restrict__ att_part,
                               const float* __restrict__ bf,
                               float* __restrict__ alpha) {
    __shared__ float sv[256];
    const int b = blockIdx.x;
    const int tid = threadIdx.x;
    float val = 0.f;
    float v = -INFINITY;
    if (tid < NPIX) {
        const int m = b * NPIX + tid;
        val = bf[0] + att_part[0 * MTOT + m] + att_part[1 * MTOT + m]
            + att_part[2 * MTOT + m] + att_part[3 * MTOT + m];
        v = val;
    }
    sv[tid] = v;
    __syncthreads();
    #pragma unroll
    for (int s = 128; s > 0; s >>= 1) {
        if (tid < s) sv[tid] = fmaxf(sv[tid], sv[tid + s]);
        __syncthreads();
    }
    const float mx = sv[0];
    __syncthreads();
    const float e = (tid < NPIX) ? expf(val - mx) : 0.f;
    sv[tid] = e;
    __syncthreads();
    #pragma unroll
    for (int s = 128; s > 0; s >>= 1) {
        if (tid < s) sv[tid] = sv[tid] + sv[tid + s];
        __syncthreads();
    }
    const float sum = sv[0];
    if (tid < NPIX) alpha[b * NPIX + tid] = e / sum;
}

// ---------------------------------------------------------------------------
// K4: out[b][c] = sum_p conv[b][p][c] * alpha[b][p]  (float4, 2 chains)
// ---------------------------------------------------------------------------
__global__ void pool_kernel(const float* __restrict__ conv,
                            const float* __restrict__ alpha,
                            float* __restrict__ out) {
    __shared__ float al[NPIX];
    const int b = blockIdx.y;
    const int c4 = blockIdx.x * 256 + threadIdx.x;
    if (threadIdx.x < NPIX) al[threadIdx.x] = alpha[b * NPIX + threadIdx.x];
    __syncthreads();
    const float4* cp = reinterpret_cast<const float4*>(conv + (size_t)b * NPIX * CDIM) + c4;
    float4 a0 = make_float4(0.f, 0.f, 0.f, 0.f);
    float4 a1 = make_float4(0.f, 0.f, 0.f, 0.f);
    #pragma unroll 4
    for (int p = 0; p < NPIX; p += 2) {
        float4 v0 = cp[(size_t)p * (CDIM / 4)];
        float4 v1 = cp[(size_t)(p + 1) * (CDIM / 4)];
        float w0 = al[p], w1 = al[p + 1];
        a0.x += v0.x * w0; a0.y += v0.y * w0; a0.z += v0.z * w0; a0.w += v0.w * w0;
        a1.x += v1.x * w1; a1.y += v1.y * w1; a1.z += v1.z * w1; a1.w += v1.w * w1;
    }
    float4 r = make_float4(a0.x + a1.x, a0.y + a1.y, a0.z + a1.z, a0.w + a1.w);
    reinterpret_cast<float4*>(out)[(size_t)b * (CDIM / 4) + c4] = r;
}

// ---------------------------------------------------------------------------
extern "C" void kernel_launch(void* const* d_in, const int* in_sizes, int n_in,
                              void* d_out, int out_size) {
    const float* conv = (const float*)d_in[0];
    const float* lstm = (const float*)d_in[1];
    const float* Wc   = (const float*)d_in[2];
    const float* bc   = (const float*)d_in[3];
    const float* Wl   = (const float*)d_in[4];
    const float* bl   = (const float*)d_in[5];
    const float* Wf   = (const float*)d_in[6];
    const float* bf   = (const float*)d_in[7];
    float* out = (float*)d_out;

    float* att2;     cudaGetSymbolAddress((void**)&att2, g_att2);
    float* att_part; cudaGetSymbolAddress((void**)&att_part, g_att_part);
    float* alpha;    cudaGetSymbolAddress((void**)&alpha, g_alpha);

    cudaFuncSetAttribute(score_gemm_kernel,
                         cudaFuncAttributeMaxDynamicSharedMemorySize, SMEM_BYTES);

    convert_wc_kernel<<<(ADIM * CDIM / 4) / 256, 256>>>(Wc);
    convert_a_kernel<<<(int)(((size_t)MTOT * CDIM / 4) / 256), 256>>>(conv);
    att2_kernel<<<BATCH / 8, LDIM>>>(lstm, Wl, bl, att2);

    dim3 gg(NBLK, MTOT / BM);
    score_gemm_kernel<<<gg, 256, SMEM_BYTES>>>(bc, Wf, att2, att_part);

    softmax_kernel<<<BATCH, 256>>>(att_part, bf, alpha);
    pool_kernel<<<dim3(CDIM / 4 / 256, BATCH), 256>>>(conv, alpha, out);
}

// round 10
// speedup vs baseline: 3.0695x; 1.6792x over previous
#include <cuda_runtime.h>
#include <cuda_fp16.h>
#include <math.h>
#include <stdint.h>

// Problem dims (fixed by the reference)
#define BATCH 256
#define NPIX  196
#define CDIM  2048
#define ADIM  512
#define LDIM  512
#define MTOT  (BATCH * NPIX)   // 50176 = 392 * 128

// GEMM tiling (mma.sync m16n8k16, fp16 in / f32 accum, single pass)
#define BM 128
#define BN 128
#define BK 32
#define NBLK (ADIM / BN)       // 4
#define NITER (CDIM / BK)      // 64
#define WM 64
#define WN 32
#define NSTAGE 4

// Scratch (device globals — no allocation allowed)
__device__ float g_att2[BATCH * ADIM];
__device__ float g_att_part[NBLK * MTOT];
__device__ float g_alpha[MTOT];
__device__ __half g_Wc_h[ADIM * CDIM];                 // fp16(Wc)
__device__ __half g_A_h[(size_t)MTOT * CDIM];          // fp16(conv_out)

// smem: row stride 80B (32 fp16 + 16B pad) — conflict-free LDSM (20 mod 32 walk)
#define ROWB 80
#define TILEB (128 * ROWB)     // 10240
#define SM_A(s) ((s) * (2 * TILEB) + 0)
#define SM_B(s) ((s) * (2 * TILEB) + TILEB)
#define SMEM_BYTES (NSTAGE * 2 * TILEB)   // 81920

__device__ __forceinline__ uint32_t smem_to_u32(const void* p) {
    uint32_t a;
    asm("{ .reg .u64 t; cvta.to.shared.u64 t, %1; cvt.u32.u64 %0, t; }" : "=r"(a) : "l"(p));
    return a;
}
__device__ __forceinline__ void ldsm4(uint32_t* r, uint32_t addr) {
    asm volatile("ldmatrix.sync.aligned.m8n8.x4.shared.b16 {%0,%1,%2,%3}, [%4];"
                 : "=r"(r[0]), "=r"(r[1]), "=r"(r[2]), "=r"(r[3]) : "r"(addr));
}
__device__ __forceinline__ void mma16816(float* c, const uint32_t* a, const uint32_t* b) {
    asm volatile("mma.sync.aligned.m16n8k16.row.col.f32.f16.f16.f32 "
                 "{%0,%1,%2,%3}, {%4,%5,%6,%7}, {%8,%9}, {%0,%1,%2,%3};"
                 : "+f"(c[0]), "+f"(c[1]), "+f"(c[2]), "+f"(c[3])
                 : "r"(a[0]), "r"(a[1]), "r"(a[2]), "r"(a[3]), "r"(b[0]), "r"(b[1]));
}
#define CP_ASYNC16(dst, src) \
    asm volatile("cp.async.cg.shared.global [%0], [%1], 16;" :: "r"(dst), "l"(src))
#define CP_COMMIT() asm volatile("cp.async.commit_group;" ::: "memory")
#define CP_WAIT2()  asm volatile("cp.async.wait_group 2;" ::: "memory")
#define CP_WAIT0()  asm volatile("cp.async.wait_group 0;" ::: "memory")

__device__ __forceinline__ uint32_t pack_h(__half a, __half b) {
    return (uint32_t)__half_as_ushort(a) | ((uint32_t)__half_as_ushort(b) << 16);
}

// ---------------------------------------------------------------------------
// K0a: convert Wc -> fp16
// ---------------------------------------------------------------------------
__global__ void convert_wc_kernel(const float* __restrict__ Wc) {
    const size_t i4 = (size_t)blockIdx.x * 256 + threadIdx.x;
    float4 v = reinterpret_cast<const float4*>(Wc)[i4];
    reinterpret_cast<uint2*>(g_Wc_h)[i4] =
        make_uint2(pack_h(__float2half(v.x), __float2half(v.y)),
                   pack_h(__float2half(v.z), __float2half(v.w)));
}

// ---------------------------------------------------------------------------
// K0b: convert conv_out -> fp16
// ---------------------------------------------------------------------------
__global__ void convert_a_kernel(const float* __restrict__ A) {
    const size_t i4 = (size_t)blockIdx.x * 256 + threadIdx.x;
    float4 v = reinterpret_cast<const float4*>(A)[i4];
    reinterpret_cast<uint2*>(g_A_h)[i4] =
        make_uint2(pack_h(__float2half(v.x), __float2half(v.y)),
                   pack_h(__float2half(v.z), __float2half(v.w)));
}

// ---------------------------------------------------------------------------
// K1: att2[b][a] = lstm[b] . Wl[a] + bl[a]
// ---------------------------------------------------------------------------
__global__ void att2_kernel(const float* __restrict__ lstm,
                            const float* __restrict__ Wl,
                            const float* __restrict__ bl,
                            float* __restrict__ att2) {
    __shared__ float h[8][LDIM];
    const int b0 = blockIdx.x * 8;
    const int a = threadIdx.x;
    #pragma unroll
    for (int i = 0; i < 8; i++) h[i][a] = lstm[(b0 + i) * LDIM + a];
    __syncthreads();
    const float4* w4 = reinterpret_cast<const float4*>(Wl + (size_t)a * LDIM);
    float acc[8] = {0.f, 0.f, 0.f, 0.f, 0.f, 0.f, 0.f, 0.f};
    #pragma unroll 4
    for (int l4 = 0; l4 < LDIM / 4; l4++) {
        float4 wv = w4[l4];
        int l = l4 * 4;
        #pragma unroll
        for (int i = 0; i < 8; i++) {
            acc[i] += h[i][l + 0] * wv.x;
            acc[i] += h[i][l + 1] * wv.y;
            acc[i] += h[i][l + 2] * wv.z;
            acc[i] += h[i][l + 3] * wv.w;
        }
    }
    const float bv = bl[a];
    #pragma unroll
    for (int i = 0; i < 8; i++) att2[(b0 + i) * ADIM + a] = acc[i] + bv;
}

// ---------------------------------------------------------------------------
// K2: fp16 single-pass score GEMM, BK=32, 4-stage cp.async, 2 CTAs/SM.
// Grid (4, 392): bn fast => 4 CTAs share one A tile via L2.
// 256 threads (8 warps 2x4), warp tile 64x32.
// ---------------------------------------------------------------------------
__global__ void __launch_bounds__(256, 2)
score_gemm_kernel(const float* __restrict__ bc,
                  const float* __restrict__ Wf,
                  const float* __restrict__ att2,   // B x 512
                  float* __restrict__ att_part)     // NBLK x M
{
    extern __shared__ char sm[];
    const uint32_t sb = smem_to_u32(sm);
    const int tid = threadIdx.x;
    const int lane = tid & 31;
    const int wid = tid >> 5;
    const int warp_m = wid >> 2;       // 0..1
    const int warp_n = wid & 3;        // 0..3
    const int bn = blockIdx.x;         // 0..3 (fast: A-tile L2 sharing)
    const int bm = blockIdx.y;         // 0..391

    // ldmatrix per-lane offsets (k-half kk adds 32 bytes)
    uint32_t aoff[4], boff[2];
    {
        const int ar = lane & 15, abyte = (lane >> 4) * 16;
        #pragma unroll
        for (int mb = 0; mb < 4; mb++)
            aoff[mb] = (uint32_t)((warp_m * WM + mb * 16 + ar) * ROWB + abyte);
        const int bnr = (lane & 7) + ((lane >> 4) << 3);
        const int bbyte = ((lane >> 3) & 1) * 16;
        #pragma unroll
        for (int g = 0; g < 2; g++)
            boff[g] = (uint32_t)((warp_n * WN + g * 16 + bnr) * ROWB + bbyte);
    }

    // cp.async: per stage, A and B are each 128 rows x 4 chunks(16B)
    // thread handles chunks idx = tid and tid+256 of each matrix
    const int r0 = tid >> 2, q0 = tid & 3;          // chunk tid
    const int r1 = (tid + 256) >> 2, q1 = tid & 3;  // chunk tid+256
    const uint32_t s_off0 = (uint32_t)(r0 * ROWB + q0 * 16);
    const uint32_t s_off1 = (uint32_t)(r1 * ROWB + q1 * 16);
    const size_t a_g0 = (size_t)(bm * BM + r0) * CDIM + q0 * 8;
    const size_t a_g1 = (size_t)(bm * BM + r1) * CDIM + q1 * 8;
    const size_t b_g0 = (size_t)(bn * BN + r0) * CDIM + q0 * 8;
    const size_t b_g1 = (size_t)(bn * BN + r1) * CDIM + q1 * 8;

    float acc[4][4][4];
    #pragma unroll
    for (int mb = 0; mb < 4; mb++)
        #pragma unroll
        for (int nb = 0; nb < 4; nb++)
            #pragma unroll
            for (int j = 0; j < 4; j++) acc[mb][nb][j] = 0.f;

    auto issue = [&](int s) {
        const int buf = s & (NSTAGE - 1);
        const int k0 = s * BK;
        CP_ASYNC16(sb + SM_A(buf) + s_off0, (const char*)(g_A_h + a_g0 + k0));
        CP_ASYNC16(sb + SM_A(buf) + s_off1, (const char*)(g_A_h + a_g1 + k0));
        CP_ASYNC16(sb + SM_B(buf) + s_off0, (const char*)(g_Wc_h + b_g0 + k0));
        CP_ASYNC16(sb + SM_B(buf) + s_off1, (const char*)(g_Wc_h + b_g1 + k0));
        CP_COMMIT();
    };

    issue(0); issue(1); issue(2);
    CP_WAIT2();            // stage 0 complete
    __syncthreads();

    #pragma unroll 1
    for (int it = 0; it < NITER; it++) {
        const int buf = it & (NSTAGE - 1);
        const bool more = (it + 3 < NITER);
        if (more) issue(it + 3);

        #pragma unroll
        for (int kk = 0; kk < 2; kk++) {
            uint32_t a[4][4], b[2][4];
            #pragma unroll
            for (int g = 0; g < 2; g++) ldsm4(b[g], sb + SM_B(buf) + boff[g] + kk * 32);
            #pragma unroll
            for (int mb = 0; mb < 4; mb++) ldsm4(a[mb], sb + SM_A(buf) + aoff[mb] + kk * 32);
            #pragma unroll
            for (int mb = 0; mb < 4; mb++)
                #pragma unroll
                for (int nb = 0; nb < 4; nb++)
                    mma16816(acc[mb][nb], a[mb], &b[nb >> 1][(nb & 1) * 2]);
        }

        if (more) { CP_WAIT2(); } else { CP_WAIT0(); }
        __syncthreads();
    }

    // ---- epilogue: relu(C + bc + att2) . Wf reduced over n ----
    float wfv[8], bcv[8];
    const int ncol0 = bn * BN + warp_n * WN;
    #pragma unroll
    for (int nb = 0; nb < 4; nb++)
        #pragma unroll
        for (int jj = 0; jj < 2; jj++) {
            const int n = ncol0 + nb * 8 + 2 * (lane & 3) + jj;
            wfv[nb * 2 + jj] = Wf[n];
            bcv[nb * 2 + jj] = bc[n];
        }

    float* red = reinterpret_cast<float*>(sm);   // [4][128]
    #pragma unroll
    for (int mb = 0; mb < 4; mb++) {
        #pragma unroll
        for (int half = 0; half < 2; half++) {
            const int m_loc = warp_m * WM + mb * 16 + (lane >> 2) + half * 8;
            const int m = bm * BM + m_loc;
            const int b = m / NPIX;
            const float* a2 = att2 + (size_t)b * ADIM + ncol0;
            float s = 0.f;
            #pragma unroll
            for (int nb = 0; nb < 4; nb++)
                #pragma unroll
                for (int jj = 0; jj < 2; jj++) {
                    const int ci = half * 2 + jj;
                    const int nrel = nb * 8 + 2 * (lane & 3) + jj;
                    float v = acc[mb][nb][ci] + bcv[nb * 2 + jj] + a2[nrel];
                    s += fmaxf(v, 0.f) * wfv[nb * 2 + jj];
                }
            s += __shfl_xor_sync(0xFFFFFFFF, s, 1);
            s += __shfl_xor_sync(0xFFFFFFFF, s, 2);
            if ((lane & 3) == 0) red[warp_n * BM + m_loc] = s;
        }
    }
    __syncthreads();
    if (tid < BM) {
        float s = red[0 * BM + tid] + red[1 * BM + tid] + red[2 * BM + tid] + red[3 * BM + tid];
        att_part[(size_t)bn * MTOT + bm * BM + tid] = s;
    }
}

// ---------------------------------------------------------------------------
// K3: softmax over P=196 per batch row (4 partials).
// ---------------------------------------------------------------------------
__global__ void softmax_kernel(const float* __restrict__ att_part,
                               const float* __restrict__ bf,
                               float* __restrict__ alpha) {
    __shared__ float sv[256];
    const int b = blockIdx.x;
    const int tid = threadIdx.x;
    float val = 0.f;
    float v = -INFINITY;
    if (tid < NPIX) {
        const int m = b * NPIX + tid;
        val = bf[0] + att_part[0 * MTOT + m] + att_part[1 * MTOT + m]
            + att_part[2 * MTOT + m] + att_part[3 * MTOT + m];
        v = val;
    }
    sv[tid] = v;
    __syncthreads();
    #pragma unroll
    for (int s = 128; s > 0; s >>= 1) {
        if (tid < s) sv[tid] = fmaxf(sv[tid], sv[tid + s]);
        __syncthreads();
    }
    const float mx = sv[0];
    __syncthreads();
    const float e = (tid < NPIX) ? expf(val - mx) : 0.f;
    sv[tid] = e;
    __syncthreads();
    #pragma unroll
    for (int s = 128; s > 0; s >>= 1) {
        if (tid < s) sv[tid] = sv[tid] + sv[tid + s];
        __syncthreads();
    }
    const float sum = sv[0];
    if (tid < NPIX) alpha[b * NPIX + tid] = e / sum;
}

// ---------------------------------------------------------------------------
// K4: out[b][c] = sum_p conv[b][p][c] * alpha[b][p]  (float4, 2 chains)
// ---------------------------------------------------------------------------
__global__ void pool_kernel(const float* __restrict__ conv,
                            const float* __restrict__ alpha,
                            float* __restrict__ out) {
    __shared__ float al[NPIX];
    const int b = blockIdx.y;
    const int c4 = blockIdx.x * 256 + threadIdx.x;
    if (threadIdx.x < NPIX) al[threadIdx.x] = alpha[b * NPIX + threadIdx.x];
    __syncthreads();
    const float4* cp = reinterpret_cast<const float4*>(conv + (size_t)b * NPIX * CDIM) + c4;
    float4 a0 = make_float4(0.f, 0.f, 0.f, 0.f);
    float4 a1 = make_float4(0.f, 0.f, 0.f, 0.f);
    #pragma unroll 4
    for (int p = 0; p < NPIX; p += 2) {
        float4 v0 = cp[(size_t)p * (CDIM / 4)];
        float4 v1 = cp[(size_t)(p + 1) * (CDIM / 4)];
        float w0 = al[p], w1 = al[p + 1];
        a0.x += v0.x * w0; a0.y += v0.y * w0; a0.z += v0.z * w0; a0.w += v0.w * w0;
        a1.x += v1.x * w1; a1.y += v1.y * w1; a1.z += v1.z * w1; a1.w += v1.w * w1;
    }
    float4 r = make_float4(a0.x + a1.x, a0.y + a1.y, a0.z + a1.z, a0.w + a1.w);
    reinterpret_cast<float4*>(out)[(size_t)b * (CDIM / 4) + c4] = r;
}

// ---------------------------------------------------------------------------
extern "C" void kernel_launch(void* const* d_in, const int* in_sizes, int n_in,
                              void* d_out, int out_size) {
    const float* conv = (const float*)d_in[0];
    const float* lstm = (const float*)d_in[1];
    const float* Wc   = (const float*)d_in[2];
    const float* bc   = (const float*)d_in[3];
    const float* Wl   = (const float*)d_in[4];
    const float* bl   = (const float*)d_in[5];
    const float* Wf   = (const float*)d_in[6];
    const float* bf   = (const float*)d_in[7];
    float* out = (float*)d_out;

    float* att2;     cudaGetSymbolAddress((void**)&att2, g_att2);
    float* att_part; cudaGetSymbolAddress((void**)&att_part, g_att_part);
    float* alpha;    cudaGetSymbolAddress((void**)&alpha, g_alpha);

    cudaFuncSetAttribute(score_gemm_kernel,
                         cudaFuncAttributeMaxDynamicSharedMemorySize, SMEM_BYTES);

    convert_wc_kernel<<<(ADIM * CDIM / 4) / 256, 256>>>(Wc);
    convert_a_kernel<<<(int)(((size_t)MTOT * CDIM / 4) / 256), 256>>>(conv);
    att2_kernel<<<BATCH / 8, LDIM>>>(lstm, Wl, bl, att2);

    dim3 gg(NBLK, MTOT / BM);
    score_gemm_kernel<<<gg, 256, SMEM_BYTES>>>(bc, Wf, att2, att_part);

    softmax_kernel<<<BATCH, 256>>>(att_part, bf, alpha);
    pool_kernel<<<dim3(CDIM / 4 / 256, BATCH), 256>>>(conv, alpha, out);
}

// round 11
// speedup vs baseline: 3.2602x; 1.0621x over previous
#include <cuda_runtime.h>
#include <cuda_fp16.h>
#include <math.h>
#include <stdint.h>

// Problem dims (fixed by the reference)
#define BATCH 256
#define NPIX  196
#define CDIM  2048
#define ADIM  512
#define LDIM  512
#define MTOT  (BATCH * NPIX)   // 50176 = 392 * 128

// GEMM tiling (mma.sync m16n8k16, fp16 in / f32 accum, single pass)
#define BM 128
#define BN 128
#define BK 64
#define NBLK (ADIM / BN)       // 4
#define NITER (CDIM / BK)      // 32
#define WM 64
#define WN 32
#define NSTAGE 3

// Scratch (device globals — no allocation allowed)
__device__ float g_att2[BATCH * ADIM];
__device__ float g_att_part[NBLK * MTOT];
__device__ float g_alpha[MTOT];
__device__ __half g_Wc_h[ADIM * CDIM];                 // fp16(Wc)
__device__ __half g_A_h[(size_t)MTOT * CDIM];          // fp16(conv_out)

// smem: row stride 144B (64 fp16 + 16B pad) — LDSM walks banks {0,4,..,28}
#define ROWB 144
#define TILEB (128 * ROWB)     // 18432
#define SM_A(s) ((s) * (2 * TILEB) + 0)
#define SM_B(s) ((s) * (2 * TILEB) + TILEB)
#define SMEM_BYTES (NSTAGE * 2 * TILEB)   // 110592

__device__ __forceinline__ uint32_t smem_to_u32(const void* p) {
    uint32_t a;
    asm("{ .reg .u64 t; cvta.to.shared.u64 t, %1; cvt.u32.u64 %0, t; }" : "=r"(a) : "l"(p));
    return a;
}
__device__ __forceinline__ void ldsm4(uint32_t* r, uint32_t addr) {
    asm volatile("ldmatrix.sync.aligned.m8n8.x4.shared.b16 {%0,%1,%2,%3}, [%4];"
                 : "=r"(r[0]), "=r"(r[1]), "=r"(r[2]), "=r"(r[3]) : "r"(addr));
}
__device__ __forceinline__ void mma16816(float* c, const uint32_t* a, const uint32_t* b) {
    asm volatile("mma.sync.aligned.m16n8k16.row.col.f32.f16.f16.f32 "
                 "{%0,%1,%2,%3}, {%4,%5,%6,%7}, {%8,%9}, {%0,%1,%2,%3};"
                 : "+f"(c[0]), "+f"(c[1]), "+f"(c[2]), "+f"(c[3])
                 : "r"(a[0]), "r"(a[1]), "r"(a[2]), "r"(a[3]), "r"(b[0]), "r"(b[1]));
}
#define CP_ASYNC16(dst, src) \
    asm volatile("cp.async.cg.shared.global [%0], [%1], 16;" :: "r"(dst), "l"(src))
#define CP_COMMIT() asm volatile("cp.async.commit_group;" ::: "memory")
#define CP_WAIT1()  asm volatile("cp.async.wait_group 1;" ::: "memory")
#define CP_WAIT0()  asm volatile("cp.async.wait_group 0;" ::: "memory")

__device__ __forceinline__ uint32_t pack_h(__half a, __half b) {
    return (uint32_t)__half_as_ushort(a) | ((uint32_t)__half_as_ushort(b) << 16);
}

// ---------------------------------------------------------------------------
// K0a: convert Wc -> fp16
// ---------------------------------------------------------------------------
__global__ void convert_wc_kernel(const float* __restrict__ Wc) {
    const size_t i4 = (size_t)blockIdx.x * 256 + threadIdx.x;
    float4 v = reinterpret_cast<const float4*>(Wc)[i4];
    reinterpret_cast<uint2*>(g_Wc_h)[i4] =
        make_uint2(pack_h(__float2half(v.x), __float2half(v.y)),
                   pack_h(__float2half(v.z), __float2half(v.w)));
}

// ---------------------------------------------------------------------------
// K0b: convert conv_out -> fp16
// ---------------------------------------------------------------------------
__global__ void convert_a_kernel(const float* __restrict__ A) {
    const size_t i4 = (size_t)blockIdx.x * 256 + threadIdx.x;
    float4 v = reinterpret_cast<const float4*>(A)[i4];
    reinterpret_cast<uint2*>(g_A_h)[i4] =
        make_uint2(pack_h(__float2half(v.x), __float2half(v.y)),
                   pack_h(__float2half(v.z), __float2half(v.w)));
}

// ---------------------------------------------------------------------------
// K1: att2[b][a] = lstm[b] . Wl[a] + bl[a]
// ---------------------------------------------------------------------------
__global__ void att2_kernel(const float* __restrict__ lstm,
                            const float* __restrict__ Wl,
                            const float* __restrict__ bl,
                            float* __restrict__ att2) {
    __shared__ float h[8][LDIM];
    const int b0 = blockIdx.x * 8;
    const int a = threadIdx.x;
    #pragma unroll
    for (int i = 0; i < 8; i++) h[i][a] = lstm[(b0 + i) * LDIM + a];
    __syncthreads();
    const float4* w4 = reinterpret_cast<const float4*>(Wl + (size_t)a * LDIM);
    float acc[8] = {0.f, 0.f, 0.f, 0.f, 0.f, 0.f, 0.f, 0.f};
    #pragma unroll 4
    for (int l4 = 0; l4 < LDIM / 4; l4++) {
        float4 wv = w4[l4];
        int l = l4 * 4;
        #pragma unroll
        for (int i = 0; i < 8; i++) {
            acc[i] += h[i][l + 0] * wv.x;
            acc[i] += h[i][l + 1] * wv.y;
            acc[i] += h[i][l + 2] * wv.z;
            acc[i] += h[i][l + 3] * wv.w;
        }
    }
    const float bv = bl[a];
    #pragma unroll
    for (int i = 0; i < 8; i++) att2[(b0 + i) * ADIM + a] = acc[i] + bv;
}

// ---------------------------------------------------------------------------
// K2: fp16 single-pass score GEMM, BK=64, 3-stage cp.async, 2 CTAs/SM.
// Grid (4, 392): bn fast => 4 CTAs share one A tile via L2.
// 256 threads (8 warps 2x4), warp tile 64x32.
// ---------------------------------------------------------------------------
__global__ void __launch_bounds__(256, 2)
score_gemm_kernel(const float* __restrict__ bc,
                  const float* __restrict__ Wf,
                  const float* __restrict__ att2,   // B x 512
                  float* __restrict__ att_part)     // NBLK x M
{
    extern __shared__ char sm[];
    const uint32_t sb = smem_to_u32(sm);
    const int tid = threadIdx.x;
    const int lane = tid & 31;
    const int wid = tid >> 5;
    const int warp_m = wid >> 2;       // 0..1
    const int warp_n = wid & 3;        // 0..3
    const int bn = blockIdx.x;         // 0..3 (fast: A-tile L2 sharing)
    const int bm = blockIdx.y;         // 0..391

    // ldmatrix per-lane offsets (k-quarter kk adds kk*32 bytes)
    uint32_t aoff[4], boff[2];
    {
        const int ar = lane & 15, abyte = (lane >> 4) * 16;
        #pragma unroll
        for (int mb = 0; mb < 4; mb++)
            aoff[mb] = (uint32_t)((warp_m * WM + mb * 16 + ar) * ROWB + abyte);
        const int bnr = (lane & 7) + ((lane >> 4) << 3);
        const int bbyte = ((lane >> 3) & 1) * 16;
        #pragma unroll
        for (int g = 0; g < 2; g++)
            boff[g] = (uint32_t)((warp_n * WN + g * 16 + bnr) * ROWB + bbyte);
    }

    // cp.async: per stage A and B are each 128 rows x 8 chunks(16B) = 1024 chunks
    // -> 4 chunks per thread per matrix
    int c_row[4]; int c_q[4]; uint32_t c_soff[4];
    #pragma unroll
    for (int i = 0; i < 4; i++) {
        const int idx = tid + 256 * i;
        c_row[i] = idx >> 3;
        c_q[i] = idx & 7;
        c_soff[i] = (uint32_t)(c_row[i] * ROWB + c_q[i] * 16);
    }

    float acc[4][4][4];
    #pragma unroll
    for (int mb = 0; mb < 4; mb++)
        #pragma unroll
        for (int nb = 0; nb < 4; nb++)
            #pragma unroll
            for (int j = 0; j < 4; j++) acc[mb][nb][j] = 0.f;

    auto issue = [&](int s) {
        const int buf = s % NSTAGE;
        const int k0 = s * BK;
        #pragma unroll
        for (int i = 0; i < 4; i++) {
            const size_t ag = (size_t)(bm * BM + c_row[i]) * CDIM + k0 + c_q[i] * 8;
            CP_ASYNC16(sb + SM_A(buf) + c_soff[i], (const char*)(g_A_h + ag));
        }
        #pragma unroll
        for (int i = 0; i < 4; i++) {
            const size_t bg = (size_t)(bn * BN + c_row[i]) * CDIM + k0 + c_q[i] * 8;
            CP_ASYNC16(sb + SM_B(buf) + c_soff[i], (const char*)(g_Wc_h + bg));
        }
        CP_COMMIT();
    };

    issue(0); issue(1);
    CP_WAIT1();            // stage 0 complete
    __syncthreads();

    #pragma unroll 1
    for (int it = 0; it < NITER; it++) {
        const int buf = it % NSTAGE;
        const bool more = (it + 2 < NITER);
        if (more) issue(it + 2);

        #pragma unroll
        for (int kk = 0; kk < 4; kk++) {
            uint32_t a[4][4], b[2][4];
            #pragma unroll
            for (int g = 0; g < 2; g++) ldsm4(b[g], sb + SM_B(buf) + boff[g] + kk * 32);
            #pragma unroll
            for (int mb = 0; mb < 4; mb++) ldsm4(a[mb], sb + SM_A(buf) + aoff[mb] + kk * 32);
            #pragma unroll
            for (int mb = 0; mb < 4; mb++)
                #pragma unroll
                for (int nb = 0; nb < 4; nb++)
                    mma16816(acc[mb][nb], a[mb], &b[nb >> 1][(nb & 1) * 2]);
        }

        if (more) { CP_WAIT1(); } else { CP_WAIT0(); }
        __syncthreads();
    }

    // ---- epilogue: relu(C + bc + att2) . Wf reduced over n ----
    float wfv[8], bcv[8];
    const int ncol0 = bn * BN + warp_n * WN;
    #pragma unroll
    for (int nb = 0; nb < 4; nb++)
        #pragma unroll
        for (int jj = 0; jj < 2; jj++) {
            const int n = ncol0 + nb * 8 + 2 * (lane & 3) + jj;
            wfv[nb * 2 + jj] = Wf[n];
            bcv[nb * 2 + jj] = bc[n];
        }

    float* red = reinterpret_cast<float*>(sm);   // [4][128]
    #pragma unroll
    for (int mb = 0; mb < 4; mb++) {
        #pragma unroll
        for (int half = 0; half < 2; half++) {
            const int m_loc = warp_m * WM + mb * 16 + (lane >> 2) + half * 8;
            const int m = bm * BM + m_loc;
            const int b = m / NPIX;
            const float* a2 = att2 + (size_t)b * ADIM + ncol0;
            float s = 0.f;
            #pragma unroll
            for (int nb = 0; nb < 4; nb++)
                #pragma unroll
                for (int jj = 0; jj < 2; jj++) {
                    const int ci = half * 2 + jj;
                    const int nrel = nb * 8 + 2 * (lane & 3) + jj;
                    float v = acc[mb][nb][ci] + bcv[nb * 2 + jj] + a2[nrel];
                    s += fmaxf(v, 0.f) * wfv[nb * 2 + jj];
                }
            s += __shfl_xor_sync(0xFFFFFFFF, s, 1);
            s += __shfl_xor_sync(0xFFFFFFFF, s, 2);
            if ((lane & 3) == 0) red[warp_n * BM + m_loc] = s;
        }
    }
    __syncthreads();
    if (tid < BM) {
        float s = red[0 * BM + tid] + red[1 * BM + tid] + red[2 * BM + tid] + red[3 * BM + tid];
        att_part[(size_t)bn * MTOT + bm * BM + tid] = s;
    }
}

// ---------------------------------------------------------------------------
// K3: softmax over P=196 per batch row (4 partials).
// ---------------------------------------------------------------------------
__global__ void softmax_kernel(const float* __restrict__ att_part,
                               const float* __restrict__ bf,
                               float* __restrict__ alpha) {
    __shared__ float sv[256];
    const int b = blockIdx.x;
    const int tid = threadIdx.x;
    float val = 0.f;
    float v = -INFINITY;
    if (tid < NPIX) {
        const int m = b * NPIX + tid;
        val = bf[0] + att_part[0 * MTOT + m] + att_part[1 * MTOT + m]
            + att_part[2 * MTOT + m] + att_part[3 * MTOT + m];
        v = val;
    }
    sv[tid] = v;
    __syncthreads();
    #pragma unroll
    for (int s = 128; s > 0; s >>= 1) {
        if (tid < s) sv[tid] = fmaxf(sv[tid], sv[tid + s]);
        __syncthreads();
    }
    const float mx = sv[0];
    __syncthreads();
    const float e = (tid < NPIX) ? expf(val - mx) : 0.f;
    sv[tid] = e;
    __syncthreads();
    #pragma unroll
    for (int s = 128; s > 0; s >>= 1) {
        if (tid < s) sv[tid] = sv[tid] + sv[tid + s];
        __syncthreads();
    }
    const float sum = sv[0];
    if (tid < NPIX) alpha[b * NPIX + tid] = e / sum;
}

// ---------------------------------------------------------------------------
// K4: out[b][c] = sum_p conv[b][p][c] * alpha[b][p]  (float4, 2 chains)
// ---------------------------------------------------------------------------
__global__ void pool_kernel(const float* __restrict__ conv,
                            const float* __restrict__ alpha,
                            float* __restrict__ out) {
    __shared__ float al[NPIX];
    const int b = blockIdx.y;
    const int c4 = blockIdx.x * 256 + threadIdx.x;
    if (threadIdx.x < NPIX) al[threadIdx.x] = alpha[b * NPIX + threadIdx.x];
    __syncthreads();
    const float4* cp = reinterpret_cast<const float4*>(conv + (size_t)b * NPIX * CDIM) + c4;
    float4 a0 = make_float4(0.f, 0.f, 0.f, 0.f);
    float4 a1 = make_float4(0.f, 0.f, 0.f, 0.f);
    #pragma unroll 4
    for (int p = 0; p < NPIX; p += 2) {
        float4 v0 = cp[(size_t)p * (CDIM / 4)];
        float4 v1 = cp[(size_t)(p + 1) * (CDIM / 4)];
        float w0 = al[p], w1 = al[p + 1];
        a0.x += v0.x * w0; a0.y += v0.y * w0; a0.z += v0.z * w0; a0.w += v0.w * w0;
        a1.x += v1.x * w1; a1.y += v1.y * w1; a1.z += v1.z * w1; a1.w += v1.w * w1;
    }
    float4 r = make_float4(a0.x + a1.x, a0.y + a1.y, a0.z + a1.z, a0.w + a1.w);
    reinterpret_cast<float4*>(out)[(size_t)b * (CDIM / 4) + c4] = r;
}

// ---------------------------------------------------------------------------
extern "C" void kernel_launch(void* const* d_in, const int* in_sizes, int n_in,
                              void* d_out, int out_size) {
    const float* conv = (const float*)d_in[0];
    const float* lstm = (const float*)d_in[1];
    const float* Wc   = (const float*)d_in[2];
    const float* bc   = (const float*)d_in[3];
    const float* Wl   = (const float*)d_in[4];
    const float* bl   = (const float*)d_in[5];
    const float* Wf   = (const float*)d_in[6];
    const float* bf   = (const float*)d_in[7];
    float* out = (float*)d_out;

    float* att2;     cudaGetSymbolAddress((void**)&att2, g_att2);
    float* att_part; cudaGetSymbolAddress((void**)&att_part, g_att_part);
    float* alpha;    cudaGetSymbolAddress((void**)&alpha, g_alpha);

    cudaFuncSetAttribute(score_gemm_kernel,
                         cudaFuncAttributeMaxDynamicSharedMemorySize, SMEM_BYTES);

    convert_wc_kernel<<<(ADIM * CDIM / 4) / 256, 256>>>(Wc);
    convert_a_kernel<<<(int)(((size_t)MTOT * CDIM / 4) / 256), 256>>>(conv);
    att2_kernel<<<BATCH / 8, LDIM>>>(lstm, Wl, bl, att2);

    dim3 gg(NBLK, MTOT / BM);
    score_gemm_kernel<<<gg, 256, SMEM_BYTES>>>(bc, Wf, att2, att_part);

    softmax_kernel<<<BATCH, 256>>>(att_part, bf, alpha);
    pool_kernel<<<dim3(CDIM / 4 / 256, BATCH), 256>>>(conv, alpha, out);
}